// round 15
// baseline (speedup 1.0000x reference)
#include <cuda_runtime.h>
#include <cuda_fp16.h>
#include <cstdint>

// ---------------- problem constants ----------------
#define BATCHES   16
#define NC_PER    1024
#define NF_PER    4096
#define NC_TOT    (BATCHES * NC_PER)   // 16384
#define NF_TOT    (BATCHES * NF_PER)   // 65536
#define C_IN      512
#define C_SKIP    256
#define D_IN      (C_IN + C_SKIP)      // 768
#define C_OUT     512
#define BN_EPS    1e-5f
#define PSTATS    256
#define HBLOCKS   ((NF_TOT * (C_OUT / 4)) / 256)   // 32768 blocks for the h-region

// ---------------- device scratch ----------------
__device__ __align__(128) __half g_h0[(size_t)NF_TOT * D_IN];
__device__ __align__(128) __half g_h1r[(size_t)NF_TOT * C_OUT];  // raw GEMM1 out (fp16)
__device__ __align__(128) __half g_h2r[(size_t)NF_TOT * C_OUT];  // raw GEMM2 out (fp16)
__device__ __align__(128) __half g_w1t[(size_t)C_OUT * D_IN];
__device__ __align__(128) __half g_w2t[(size_t)C_OUT * C_OUT];
__device__ int   g_kidx[(size_t)NF_TOT * 3];
__device__ float g_kw[(size_t)NF_TOT * 3];
__device__ float g_psum[PSTATS * C_OUT];
__device__ float g_psq[PSTATS * C_OUT];
__device__ float g_a1[C_OUT], g_c1[C_OUT], g_a2[C_OUT], g_c2[C_OUT];

// ---------------- helpers ----------------
__device__ __forceinline__ uint32_t smem_u32(const void* p) {
    uint32_t a;
    asm("{ .reg .u64 t; cvta.to.shared.u64 t, %1; cvt.u32.u64 %0, t; }" : "=r"(a) : "l"(p));
    return a;
}
__device__ __forceinline__ void cp16(uint32_t dst, const void* src) {
    asm volatile("cp.async.cg.shared.global [%0], [%1], 16;" :: "r"(dst), "l"(src));
}
__device__ __forceinline__ void cp_commit() {
    asm volatile("cp.async.commit_group;" ::: "memory");
}
__device__ __forceinline__ void cp_wait1() {
    asm volatile("cp.async.wait_group 1;" ::: "memory");
}
__device__ __forceinline__ void ldsm4(uint32_t& r0, uint32_t& r1, uint32_t& r2, uint32_t& r3, uint32_t addr) {
    asm volatile("ldmatrix.sync.aligned.m8n8.x4.shared.b16 {%0,%1,%2,%3}, [%4];"
                 : "=r"(r0), "=r"(r1), "=r"(r2), "=r"(r3) : "r"(addr));
}
__device__ __forceinline__ void mma16816(float* c, const uint32_t* a, const uint32_t* b) {
    asm volatile("mma.sync.aligned.m16n8k16.row.col.f32.f16.f16.f32 "
                 "{%0,%1,%2,%3}, {%4,%5,%6,%7}, {%8,%9}, {%0,%1,%2,%3};"
                 : "+f"(c[0]), "+f"(c[1]), "+f"(c[2]), "+f"(c[3])
                 : "r"(a[0]), "r"(a[1]), "r"(a[2]), "r"(a[3]), "r"(b[0]), "r"(b[1]));
}

// ---------------- kNN (K=3) ----------------
__global__ __launch_bounds__(256) void knn_kernel(
    const float* __restrict__ pos, const float* __restrict__ pos_skip,
    int* __restrict__ idx_out, float* __restrict__ w_out)
{
    __shared__ float sx[NC_PER], sy[NC_PER], sz[NC_PER], sn[NC_PER];
    int blk = blockIdx.x;
    int b = blk >> 4;
    const float* pc = pos + (size_t)b * NC_PER * 3;
    for (int i = threadIdx.x; i < NC_PER; i += 256) {
        float px = pc[i*3+0], py = pc[i*3+1], pz = pc[i*3+2];
        sx[i] = px; sy[i] = py; sz[i] = pz;
        sn[i] = px*px + py*py + pz*pz;
    }
    __syncthreads();
    int f = blk * 256 + threadIdx.x;
    float fx = pos_skip[f*3+0], fy = pos_skip[f*3+1], fz = pos_skip[f*3+2];
    float fn = fx*fx + fy*fy + fz*fz;
    float d0 = 3.4e38f, d1 = 3.4e38f, d2 = 3.4e38f;
    int   i0 = 0, i1 = 0, i2 = 0;
    for (int c = 0; c < NC_PER; ++c) {
        float dot = fx*sx[c] + fy*sy[c] + fz*sz[c];
        float dd  = fn + sn[c] - 2.0f*dot;
        if (dd < d2) {
            if (dd < d1) {
                if (dd < d0) { d2=d1; i2=i1; d1=d0; i1=i0; d0=dd; i0=c; }
                else         { d2=d1; i2=i1; d1=dd; i1=c; }
            } else           { d2=dd; i2=c; }
        }
    }
    float w0 = 1.0f / fmaxf(d0, 1e-16f);
    float w1 = 1.0f / fmaxf(d1, 1e-16f);
    float w2 = 1.0f / fmaxf(d2, 1e-16f);
    float inv = 1.0f / (w0 + w1 + w2);
    idx_out[f*3+0] = b * NC_PER + i0;
    idx_out[f*3+1] = b * NC_PER + i1;
    idx_out[f*3+2] = b * NC_PER + i2;
    w_out[f*3+0] = w0 * inv;
    w_out[f*3+1] = w1 * inv;
    w_out[f*3+2] = w2 * inv;
}

// ---------------- interpolate + concat -> fp16 h0 ----------------
__global__ __launch_bounds__(128) void interp_kernel(
    const float* __restrict__ x, const float* __restrict__ x_skip)
{
    int f = blockIdx.x;
    int t = threadIdx.x;
    int ia = g_kidx[f*3+0], ib = g_kidx[f*3+1], ic = g_kidx[f*3+2];
    float w0 = g_kw[f*3+0], w1 = g_kw[f*3+1], w2 = g_kw[f*3+2];
    float4 a = ((const float4*)(x + (size_t)ia * C_IN))[t];
    float4 b = ((const float4*)(x + (size_t)ib * C_IN))[t];
    float4 c = ((const float4*)(x + (size_t)ic * C_IN))[t];
    __half h[4];
    h[0] = __float2half_rn(w0*a.x + w1*b.x + w2*c.x);
    h[1] = __float2half_rn(w0*a.y + w1*b.y + w2*c.y);
    h[2] = __float2half_rn(w0*a.z + w1*b.z + w2*c.z);
    h[3] = __float2half_rn(w0*a.w + w1*b.w + w2*c.w);
    *(uint2*)(g_h0 + (size_t)f * D_IN + t * 4) = *(uint2*)h;
    if (t < C_SKIP / 4) {
        float4 s = ((const float4*)(x_skip + (size_t)f * C_SKIP))[t];
        h[0] = __float2half_rn(s.x);
        h[1] = __float2half_rn(s.y);
        h[2] = __float2half_rn(s.z);
        h[3] = __float2half_rn(s.w);
        *(uint2*)(g_h0 + (size_t)f * D_IN + C_IN + t * 4) = *(uint2*)h;
    }
}

// ---------------- W transpose -> fp16: Wt[n][k] = W[k][n] ----------------
__global__ __launch_bounds__(256) void wsplit_kernel(
    const float* __restrict__ W, __half* __restrict__ hi, int Kd, int N)
{
    int id = blockIdx.x * 256 + threadIdx.x;
    if (id >= N * Kd) return;
    int n = id / Kd, k = id % Kd;
    hi[id] = __float2half_rn(W[(size_t)k * N + n]);
}

// ---------------- fp16 HGEMM: 128(M)x256(N) tile, 512 thr, 3-stage, fp16 out ----------------
// C[M,512] = A[M,Kd] @ Wt[512,Kd]^T       (bias dropped: BN shift-invariant)
// FUSE=1: A tile transformed in smem after arrival: a' = fp16(relu(alpha[k]*a + cnst[k]))
//         (bit-identical to the standalone h1split pass it replaces)
#define BK 64
#define A_BYTES 16384                    // 128x64 fp16
#define B_BYTES 32768                    // 256x64 fp16
#define STAGE_BYTES (A_BYTES + B_BYTES)  // 49152
#define STAGES 3
#define GEMM_SMEM (STAGES * STAGE_BYTES) // 147456

__device__ __forceinline__ uint32_t swoff(int row, int c) {
    return (uint32_t)(row * 128 + ((c ^ (row & 7)) << 4));
}

template<int FUSE>
__global__ __launch_bounds__(512, 1) void gemm_kernel(
    const __half* __restrict__ A, const __half* __restrict__ B,
    __half* __restrict__ C,
    const float* __restrict__ alpha, const float* __restrict__ cnst,
    int Kd, int nchunk)
{
    extern __shared__ __align__(128) char smem[];
    __shared__ float s_a[C_OUT], s_c[C_OUT];
    uint32_t sbase = smem_u32(smem);
    int tid  = threadIdx.x;
    int wid  = tid >> 5, lane = tid & 31;
    int m0 = blockIdx.y * 128;
    int n0 = blockIdx.x * 256;

    if (FUSE) {
        s_a[tid] = alpha[tid];
        s_c[tid] = cnst[tid];
        // tid covers 0..511 == C_OUT; no sync needed yet (first use after cp_wait sync)
    }

    const __half* asrc = A + (size_t)m0 * Kd;
    const __half* bsrc = B + (size_t)n0 * Kd;

    auto issue = [&](int sidx, int k0) {
        uint32_t sb = sbase + (uint32_t)sidx * STAGE_BYTES;
        #pragma unroll
        for (int it = 0; it < 2; ++it) {             // A: 128 rows x 8 chunks
            int chunk = it * 512 + tid;
            int row = chunk >> 3, c = chunk & 7;
            cp16(sb + swoff(row, c), asrc + (size_t)row * Kd + k0 + c * 8);
        }
        uint32_t rb = sb + A_BYTES;                  // B: 256 rows x 8 chunks
        #pragma unroll
        for (int it = 0; it < 4; ++it) {
            int chunk = it * 512 + tid;
            int row = chunk >> 3, c = chunk & 7;
            cp16(rb + swoff(row, c), bsrc + (size_t)row * Kd + k0 + c * 8);
        }
    };

    issue(0, 0);   cp_commit();
    issue(1, BK);  cp_commit();

    // warp tiling: 4 (M) x 4 (N) warps; warp tile 32(M) x 64(N)
    int wm = wid & 3, wn = wid >> 2;
    int mbase = wm * 32, nbase = wn * 64;
    int sub = lane >> 3, l7 = lane & 7;

    float acc[2][8][4];
    #pragma unroll
    for (int i = 0; i < 2; ++i)
        #pragma unroll
        for (int j = 0; j < 8; ++j)
            #pragma unroll
            for (int q = 0; q < 4; ++q) acc[i][j][q] = 0.0f;

    int arow_l = mbase + ((sub & 1) << 3) + l7;
    int acol_s = (sub >> 1);
    int brow_l = nbase + ((sub >> 1) << 3) + l7;
    int bcol_s = (sub & 1);

    for (int cc = 0; cc < nchunk; ++cc) {
        cp_wait1();
        __syncthreads();
        uint32_t bb = sbase + (uint32_t)(cc % STAGES) * STAGE_BYTES;
        if (FUSE) {
            // in-place BN1+ReLU transform of the A tile (raw h1 -> activated fp16)
            int k0 = cc * BK;
            #pragma unroll
            for (int it = 0; it < 2; ++it) {
                int chunk = it * 512 + tid;
                int row = chunk >> 3, c = chunk & 7;
                uint32_t addr = bb + swoff(row, c);
                uint32_t w[4];
                asm volatile("ld.shared.v4.b32 {%0,%1,%2,%3}, [%4];"
                             : "=r"(w[0]), "=r"(w[1]), "=r"(w[2]), "=r"(w[3]) : "r"(addr));
                int kb = k0 + c * 8;
                #pragma unroll
                for (int j = 0; j < 4; ++j) {
                    float2 v = __half22float2(*(__half2*)&w[j]);
                    float y0 = fmaxf(fmaf(s_a[kb + 2*j],     v.x, s_c[kb + 2*j]),     0.0f);
                    float y1 = fmaxf(fmaf(s_a[kb + 2*j + 1], v.y, s_c[kb + 2*j + 1]), 0.0f);
                    __half2 hv = __floats2half2_rn(y0, y1);
                    w[j] = *(uint32_t*)&hv;
                }
                asm volatile("st.shared.v4.b32 [%0], {%1,%2,%3,%4};"
                             :: "r"(addr), "r"(w[0]), "r"(w[1]), "r"(w[2]), "r"(w[3]));
            }
        }
        if (cc + 2 < nchunk) issue((cc + 2) % STAGES, (cc + 2) * BK);
        cp_commit();
        if (FUSE) __syncthreads();   // transformed A visible to all warps' ldsm

        #pragma unroll
        for (int ks = 0; ks < 4; ++ks) {
            int achunk = ks * 2 + acol_s;
            int bchunk = ks * 2 + bcol_s;
            uint32_t ah[2][4], bh[8][2];
            #pragma unroll
            for (int mi = 0; mi < 2; ++mi) {
                uint32_t ao = swoff(arow_l + mi * 16, achunk);
                ldsm4(ah[mi][0], ah[mi][1], ah[mi][2], ah[mi][3], bb + ao);
            }
            #pragma unroll
            for (int pi = 0; pi < 4; ++pi) {
                uint32_t bo = swoff(brow_l + pi * 16, bchunk);
                ldsm4(bh[pi*2][0], bh[pi*2][1], bh[pi*2+1][0], bh[pi*2+1][1],
                      bb + A_BYTES + bo);
            }
            #pragma unroll
            for (int mi = 0; mi < 2; ++mi)
                #pragma unroll
                for (int ni = 0; ni < 8; ++ni)
                    mma16816(acc[mi][ni], ah[mi], bh[ni]);
        }
    }

    // ---- epilogue: fp16 (half2) store ----
    int grow = m0 + mbase + (lane >> 2);
    int gcol0 = n0 + nbase + (lane & 3) * 2;
    #pragma unroll
    for (int ni = 0; ni < 8; ++ni) {
        int col = gcol0 + ni * 8;
        #pragma unroll
        for (int mi = 0; mi < 2; ++mi) {
            int r = grow + mi * 16;
            *(__half2*)(C + (size_t)r * C_OUT + col) =
                __floats2half2_rn(acc[mi][ni][0], acc[mi][ni][1]);
            *(__half2*)(C + (size_t)(r + 8) * C_OUT + col) =
                __floats2half2_rn(acc[mi][ni][2], acc[mi][ni][3]);
        }
    }
}

// ---------------- BN stats from fp16 H (two-stage, deterministic) ----------------
// thread t covers channels 2t, 2t+1 (one half2 per row)
__global__ __launch_bounds__(256) void stats_kernel(const __half* __restrict__ H)
{
    int r0 = blockIdx.x * 256;
    int t = threadIdx.x;
    float s0 = 0, q0 = 0, s1 = 0, q1 = 0;
    const __half2* H2 = (const __half2*)H;
    for (int r = r0; r < r0 + 256; ++r) {
        float2 v = __half22float2(H2[(size_t)r * (C_OUT/2) + t]);
        s0 += v.x; q0 += v.x*v.x;
        s1 += v.y; q1 += v.y*v.y;
    }
    g_psum[blockIdx.x * C_OUT + 2*t]     = s0;
    g_psq [blockIdx.x * C_OUT + 2*t]     = q0;
    g_psum[blockIdx.x * C_OUT + 2*t + 1] = s1;
    g_psq [blockIdx.x * C_OUT + 2*t + 1] = q1;
}

__global__ __launch_bounds__(128) void finalize_kernel(
    const float* __restrict__ g, const float* __restrict__ be,
    float* __restrict__ a, float* __restrict__ c)
{
    int ch = blockIdx.x * 128 + threadIdx.x;
    float s = 0, q = 0;
    for (int p = 0; p < PSTATS; ++p) {
        s += g_psum[p * C_OUT + ch];
        q += g_psq [p * C_OUT + ch];
    }
    float mu  = s * (1.0f / NF_TOT);
    float var = q * (1.0f / NF_TOT) - mu * mu;
    float av  = g[ch] * rsqrtf(var + BN_EPS);
    a[ch] = av;
    c[ch] = be[ch] - mu * av;
}

// ---------------- final BN2 + ReLU + tuple extras (fused, disjoint block ranges) ----------------
__global__ __launch_bounds__(256) void apply_out_kernel(
    const __half* __restrict__ H, const float* __restrict__ pos_skip,
    float* __restrict__ out, int mode)
{
    if (blockIdx.x < HBLOCKS) {
        size_t i = (size_t)blockIdx.x * 256 + threadIdx.x;   // one uint2 = 4 halves
        int cb = (int)(i & (C_OUT/4 - 1));
        uint2 w = ((const uint2*)H)[i];
        float4 av = ((const float4*)g_a2)[cb];
        float4 cv = ((const float4*)g_c2)[cb];
        float2 v0 = __half22float2(*(__half2*)&w.x);
        float2 v1 = __half22float2(*(__half2*)&w.y);
        float4 r;
        r.x = fmaxf(fmaf(av.x, v0.x, cv.x), 0.0f);
        r.y = fmaxf(fmaf(av.y, v0.y, cv.y), 0.0f);
        r.z = fmaxf(fmaf(av.z, v1.x, cv.z), 0.0f);
        r.w = fmaxf(fmaf(av.w, v1.y, cv.w), 0.0f);
        ((float4*)out)[i] = r;
    } else {
        int i = (blockIdx.x - HBLOCKS) * 256 + threadIdx.x;
        const size_t baseH = (size_t)NF_TOT * C_OUT;
        if (i < NF_TOT * 3) out[baseH + i] = pos_skip[i];
        if (i < NF_TOT) {
            if (mode == 1)
                out[baseH + NF_TOT*3 + i] = (float)(i >> 12);
            else if (mode == 2)
                ((long long*)(out + baseH + NF_TOT*3))[i] = (long long)(i >> 12);
        }
    }
}

// ---------------- host ----------------
extern "C" void kernel_launch(void* const* d_in, const int* in_sizes, int n_in,
                              void* d_out, int out_size)
{
    const float* x        = (const float*)d_in[0];
    const float* pos      = (const float*)d_in[1];
    const float* x_skip   = (const float*)d_in[3];
    const float* pos_skip = (const float*)d_in[4];
    const float* W1  = (const float*)d_in[6];
    const float* g1  = (const float*)d_in[8];
    const float* be1 = (const float*)d_in[9];
    const float* W2  = (const float*)d_in[10];
    const float* g2  = (const float*)d_in[12];
    const float* be2 = (const float*)d_in[13];
    float* out = (float*)d_out;

    float *p_a1, *p_c1, *p_a2, *p_c2;
    cudaGetSymbolAddress((void**)&p_a1, g_a1);
    cudaGetSymbolAddress((void**)&p_c1, g_c1);
    cudaGetSymbolAddress((void**)&p_a2, g_a2);
    cudaGetSymbolAddress((void**)&p_c2, g_c2);
    int *p_kidx; float *p_kw;
    cudaGetSymbolAddress((void**)&p_kidx, g_kidx);
    cudaGetSymbolAddress((void**)&p_kw,   g_kw);
    __half *p_h0, *p_h1r, *p_h2r, *p_w1t, *p_w2t;
    cudaGetSymbolAddress((void**)&p_h0, g_h0);
    cudaGetSymbolAddress((void**)&p_h1r, g_h1r);
    cudaGetSymbolAddress((void**)&p_h2r, g_h2r);
    cudaGetSymbolAddress((void**)&p_w1t, g_w1t);
    cudaGetSymbolAddress((void**)&p_w2t, g_w2t);

    cudaFuncSetAttribute(gemm_kernel<0>, cudaFuncAttributeMaxDynamicSharedMemorySize, GEMM_SMEM);
    cudaFuncSetAttribute(gemm_kernel<1>, cudaFuncAttributeMaxDynamicSharedMemorySize, GEMM_SMEM);

    // weight prep (transpose + fp16)
    wsplit_kernel<<<(C_OUT * D_IN + 255) / 256, 256>>>(W1, p_w1t, D_IN, C_OUT);
    wsplit_kernel<<<(C_OUT * C_OUT + 255) / 256, 256>>>(W2, p_w2t, C_OUT, C_OUT);
    // 1) kNN
    knn_kernel<<<NF_TOT / 256, 256>>>(pos, pos_skip, p_kidx, p_kw);
    // 2) interpolate + concat -> h0 (fp16)
    interp_kernel<<<NF_TOT, 128>>>(x, x_skip);
    // 3) GEMM1 -> h1 raw fp16
    {
        dim3 grid(C_OUT / 256, NF_TOT / 128);
        gemm_kernel<0><<<grid, 512, GEMM_SMEM>>>(p_h0, p_w1t, p_h1r,
                                                 nullptr, nullptr, D_IN, D_IN / BK);
    }
    // 4) BN1 stats (fp16) + affine coefs
    stats_kernel<<<NF_TOT / 256, 256>>>(p_h1r);
    finalize_kernel<<<C_OUT / 128, 128>>>(g1, be1, p_a1, p_c1);
    // 5) GEMM2 with fused BN1+ReLU smem transform -> h2 raw fp16
    {
        dim3 grid(C_OUT / 256, NF_TOT / 128);
        gemm_kernel<1><<<grid, 512, GEMM_SMEM>>>(p_h1r, p_w2t, p_h2r,
                                                 p_a1, p_c1, C_OUT, C_OUT / BK);
    }
    // 6) BN2 stats (fp16) + affine coefs
    stats_kernel<<<NF_TOT / 256, 256>>>(p_h2r);
    finalize_kernel<<<C_OUT / 128, 128>>>(g2, be2, p_a2, p_c2);
    // 7) BN2 + ReLU -> out, fused with tuple extras
    {
        long long baseH = (long long)NF_TOT * C_OUT;
        long long rem = (long long)out_size - baseH - (long long)NF_TOT * 3;
        int mode = 0;
        if (rem >= 2LL * NF_TOT)      mode = 2;
        else if (rem >= (long long)NF_TOT) mode = 1;
        int xblocks = 0;
        if ((long long)out_size >= baseH + (long long)NF_TOT * 3)
            xblocks = (NF_TOT * 3 + 255) / 256;
        apply_out_kernel<<<HBLOCKS + xblocks, 256>>>(p_h2r, pos_skip, out, mode);
    }
}

// round 16
// speedup vs baseline: 1.0041x; 1.0041x over previous
#include <cuda_runtime.h>
#include <cuda_fp16.h>
#include <cstdint>

// ---------------- problem constants ----------------
#define BATCHES   16
#define NC_PER    1024
#define NF_PER    4096
#define NC_TOT    (BATCHES * NC_PER)   // 16384
#define NF_TOT    (BATCHES * NF_PER)   // 65536
#define C_IN      512
#define C_SKIP    256
#define D_IN      (C_IN + C_SKIP)      // 768
#define C_OUT     512
#define BN_EPS    1e-5f
#define PSTATS    256
#define HBLOCKS   ((NF_TOT * (C_OUT / 4)) / 256)   // 32768 blocks for the h-region

// ---------------- device scratch ----------------
__device__ __align__(128) __half g_h0[(size_t)NF_TOT * D_IN];
__device__ __align__(128) __half g_h1r[(size_t)NF_TOT * C_OUT];  // raw GEMM1 out (fp16)
__device__ __align__(128) __half g_h1h[(size_t)NF_TOT * C_OUT];  // post-BN1 fp16 (GEMM2 A)
__device__ __align__(128) __half g_h2r[(size_t)NF_TOT * C_OUT];  // raw GEMM2 out (fp16)
__device__ __align__(128) __half g_w1t[(size_t)C_OUT * D_IN];
__device__ __align__(128) __half g_w2t[(size_t)C_OUT * C_OUT];
__device__ int   g_kidx[(size_t)NF_TOT * 3];
__device__ float g_kw[(size_t)NF_TOT * 3];
__device__ float g_psum[PSTATS * C_OUT];
__device__ float g_psq[PSTATS * C_OUT];
__device__ float g_a1[C_OUT], g_c1[C_OUT], g_a2[C_OUT], g_c2[C_OUT];

// ---------------- helpers ----------------
__device__ __forceinline__ uint32_t smem_u32(const void* p) {
    uint32_t a;
    asm("{ .reg .u64 t; cvta.to.shared.u64 t, %1; cvt.u32.u64 %0, t; }" : "=r"(a) : "l"(p));
    return a;
}
__device__ __forceinline__ void cp16(uint32_t dst, const void* src) {
    asm volatile("cp.async.cg.shared.global [%0], [%1], 16;" :: "r"(dst), "l"(src));
}
__device__ __forceinline__ void cp_commit() {
    asm volatile("cp.async.commit_group;" ::: "memory");
}
__device__ __forceinline__ void cp_wait1() {
    asm volatile("cp.async.wait_group 1;" ::: "memory");
}
__device__ __forceinline__ void ldsm4(uint32_t& r0, uint32_t& r1, uint32_t& r2, uint32_t& r3, uint32_t addr) {
    asm volatile("ldmatrix.sync.aligned.m8n8.x4.shared.b16 {%0,%1,%2,%3}, [%4];"
                 : "=r"(r0), "=r"(r1), "=r"(r2), "=r"(r3) : "r"(addr));
}
__device__ __forceinline__ void mma16816(float* c, const uint32_t* a, const uint32_t* b) {
    asm volatile("mma.sync.aligned.m16n8k16.row.col.f32.f16.f16.f32 "
                 "{%0,%1,%2,%3}, {%4,%5,%6,%7}, {%8,%9}, {%0,%1,%2,%3};"
                 : "+f"(c[0]), "+f"(c[1]), "+f"(c[2]), "+f"(c[3])
                 : "r"(a[0]), "r"(a[1]), "r"(a[2]), "r"(a[3]), "r"(b[0]), "r"(b[1]));
}

// ---------------- kNN (K=3) ----------------
__global__ __launch_bounds__(256) void knn_kernel(
    const float* __restrict__ pos, const float* __restrict__ pos_skip,
    int* __restrict__ idx_out, float* __restrict__ w_out)
{
    __shared__ float sx[NC_PER], sy[NC_PER], sz[NC_PER], sn[NC_PER];
    int blk = blockIdx.x;
    int b = blk >> 4;
    const float* pc = pos + (size_t)b * NC_PER * 3;
    for (int i = threadIdx.x; i < NC_PER; i += 256) {
        float px = pc[i*3+0], py = pc[i*3+1], pz = pc[i*3+2];
        sx[i] = px; sy[i] = py; sz[i] = pz;
        sn[i] = px*px + py*py + pz*pz;
    }
    __syncthreads();
    int f = blk * 256 + threadIdx.x;
    float fx = pos_skip[f*3+0], fy = pos_skip[f*3+1], fz = pos_skip[f*3+2];
    float fn = fx*fx + fy*fy + fz*fz;
    float d0 = 3.4e38f, d1 = 3.4e38f, d2 = 3.4e38f;
    int   i0 = 0, i1 = 0, i2 = 0;
    for (int c = 0; c < NC_PER; ++c) {
        float dot = fx*sx[c] + fy*sy[c] + fz*sz[c];
        float dd  = fn + sn[c] - 2.0f*dot;
        if (dd < d2) {
            if (dd < d1) {
                if (dd < d0) { d2=d1; i2=i1; d1=d0; i1=i0; d0=dd; i0=c; }
                else         { d2=d1; i2=i1; d1=dd; i1=c; }
            } else           { d2=dd; i2=c; }
        }
    }
    float w0 = 1.0f / fmaxf(d0, 1e-16f);
    float w1 = 1.0f / fmaxf(d1, 1e-16f);
    float w2 = 1.0f / fmaxf(d2, 1e-16f);
    float inv = 1.0f / (w0 + w1 + w2);
    idx_out[f*3+0] = b * NC_PER + i0;
    idx_out[f*3+1] = b * NC_PER + i1;
    idx_out[f*3+2] = b * NC_PER + i2;
    w_out[f*3+0] = w0 * inv;
    w_out[f*3+1] = w1 * inv;
    w_out[f*3+2] = w2 * inv;
}

// ---------------- interpolate + concat -> fp16 h0 ----------------
__global__ __launch_bounds__(128) void interp_kernel(
    const float* __restrict__ x, const float* __restrict__ x_skip)
{
    int f = blockIdx.x;
    int t = threadIdx.x;
    int ia = g_kidx[f*3+0], ib = g_kidx[f*3+1], ic = g_kidx[f*3+2];
    float w0 = g_kw[f*3+0], w1 = g_kw[f*3+1], w2 = g_kw[f*3+2];
    float4 a = ((const float4*)(x + (size_t)ia * C_IN))[t];
    float4 b = ((const float4*)(x + (size_t)ib * C_IN))[t];
    float4 c = ((const float4*)(x + (size_t)ic * C_IN))[t];
    __half h[4];
    h[0] = __float2half_rn(w0*a.x + w1*b.x + w2*c.x);
    h[1] = __float2half_rn(w0*a.y + w1*b.y + w2*c.y);
    h[2] = __float2half_rn(w0*a.z + w1*b.z + w2*c.z);
    h[3] = __float2half_rn(w0*a.w + w1*b.w + w2*c.w);
    *(uint2*)(g_h0 + (size_t)f * D_IN + t * 4) = *(uint2*)h;
    if (t < C_SKIP / 4) {
        float4 s = ((const float4*)(x_skip + (size_t)f * C_SKIP))[t];
        h[0] = __float2half_rn(s.x);
        h[1] = __float2half_rn(s.y);
        h[2] = __float2half_rn(s.z);
        h[3] = __float2half_rn(s.w);
        *(uint2*)(g_h0 + (size_t)f * D_IN + C_IN + t * 4) = *(uint2*)h;
    }
}

// ---------------- W transpose -> fp16: Wt[n][k] = W[k][n] ----------------
__global__ __launch_bounds__(256) void wsplit_kernel(
    const float* __restrict__ W, __half* __restrict__ hi, int Kd, int N)
{
    int id = blockIdx.x * 256 + threadIdx.x;
    if (id >= N * Kd) return;
    int n = id / Kd, k = id % Kd;
    hi[id] = __float2half_rn(W[(size_t)k * N + n]);
}

// ---------------- h1r (fp16) -> BN1+ReLU -> fp16 ----------------
__global__ __launch_bounds__(256) void h1split_kernel()
{
    size_t i = (size_t)blockIdx.x * 256 + threadIdx.x;   // one uint2 = 4 halves
    int cb = (int)(i & (C_OUT/4 - 1));
    uint2 w = ((const uint2*)g_h1r)[i];
    float4 av = ((const float4*)g_a1)[cb];
    float4 cv = ((const float4*)g_c1)[cb];
    float2 v0 = __half22float2(*(__half2*)&w.x);
    float2 v1 = __half22float2(*(__half2*)&w.y);
    __half h[4];
    h[0] = __float2half_rn(fmaxf(fmaf(av.x, v0.x, cv.x), 0.0f));
    h[1] = __float2half_rn(fmaxf(fmaf(av.y, v0.y, cv.y), 0.0f));
    h[2] = __float2half_rn(fmaxf(fmaf(av.z, v1.x, cv.z), 0.0f));
    h[3] = __float2half_rn(fmaxf(fmaf(av.w, v1.y, cv.w), 0.0f));
    ((uint2*)g_h1h)[i] = *(uint2*)h;
}

// ---------------- fp16 HGEMM: 128(M)x256(N) tile, 512 thr, 3-stage, fp16 out ----------------
// C[M,512] = A[M,Kd] @ Wt[512,Kd]^T       (bias dropped: BN shift-invariant)
#define BK 64
#define A_BYTES 16384                    // 128x64 fp16
#define B_BYTES 32768                    // 256x64 fp16
#define STAGE_BYTES (A_BYTES + B_BYTES)  // 49152
#define STAGES 3
#define GEMM_SMEM (STAGES * STAGE_BYTES) // 147456

__device__ __forceinline__ uint32_t swoff(int row, int c) {
    return (uint32_t)(row * 128 + ((c ^ (row & 7)) << 4));
}

__global__ __launch_bounds__(512, 1) void gemm_kernel(
    const __half* __restrict__ A, const __half* __restrict__ B,
    __half* __restrict__ C, int Kd, int nchunk)
{
    extern __shared__ __align__(128) char smem[];
    uint32_t sbase = smem_u32(smem);
    int tid  = threadIdx.x;
    int wid  = tid >> 5, lane = tid & 31;
    int m0 = blockIdx.y * 128;
    int n0 = blockIdx.x * 256;

    const __half* asrc = A + (size_t)m0 * Kd;
    const __half* bsrc = B + (size_t)n0 * Kd;

    auto issue = [&](int sidx, int k0) {
        uint32_t sb = sbase + (uint32_t)sidx * STAGE_BYTES;
        #pragma unroll
        for (int it = 0; it < 2; ++it) {             // A: 128 rows x 8 chunks
            int chunk = it * 512 + tid;
            int row = chunk >> 3, c = chunk & 7;
            cp16(sb + swoff(row, c), asrc + (size_t)row * Kd + k0 + c * 8);
        }
        uint32_t rb = sb + A_BYTES;                  // B: 256 rows x 8 chunks
        #pragma unroll
        for (int it = 0; it < 4; ++it) {
            int chunk = it * 512 + tid;
            int row = chunk >> 3, c = chunk & 7;
            cp16(rb + swoff(row, c), bsrc + (size_t)row * Kd + k0 + c * 8);
        }
    };

    issue(0, 0);   cp_commit();
    issue(1, BK);  cp_commit();

    // warp tiling: 4 (M) x 4 (N) warps; warp tile 32(M) x 64(N)
    int wm = wid & 3, wn = wid >> 2;
    int mbase = wm * 32, nbase = wn * 64;
    int sub = lane >> 3, l7 = lane & 7;

    float acc[2][8][4];
    #pragma unroll
    for (int i = 0; i < 2; ++i)
        #pragma unroll
        for (int j = 0; j < 8; ++j)
            #pragma unroll
            for (int q = 0; q < 4; ++q) acc[i][j][q] = 0.0f;

    int arow_l = mbase + ((sub & 1) << 3) + l7;
    int acol_s = (sub >> 1);
    int brow_l = nbase + ((sub >> 1) << 3) + l7;
    int bcol_s = (sub & 1);

    for (int cc = 0; cc < nchunk; ++cc) {
        cp_wait1();
        __syncthreads();
        if (cc + 2 < nchunk) issue((cc + 2) % STAGES, (cc + 2) * BK);
        cp_commit();

        uint32_t bb = sbase + (uint32_t)(cc % STAGES) * STAGE_BYTES;
        #pragma unroll
        for (int ks = 0; ks < 4; ++ks) {
            int achunk = ks * 2 + acol_s;
            int bchunk = ks * 2 + bcol_s;
            uint32_t ah[2][4], bh[8][2];
            #pragma unroll
            for (int mi = 0; mi < 2; ++mi) {
                uint32_t ao = swoff(arow_l + mi * 16, achunk);
                ldsm4(ah[mi][0], ah[mi][1], ah[mi][2], ah[mi][3], bb + ao);
            }
            #pragma unroll
            for (int pi = 0; pi < 4; ++pi) {
                uint32_t bo = swoff(brow_l + pi * 16, bchunk);
                ldsm4(bh[pi*2][0], bh[pi*2][1], bh[pi*2+1][0], bh[pi*2+1][1],
                      bb + A_BYTES + bo);
            }
            #pragma unroll
            for (int mi = 0; mi < 2; ++mi)
                #pragma unroll
                for (int ni = 0; ni < 8; ++ni)
                    mma16816(acc[mi][ni], ah[mi], bh[ni]);
        }
    }

    // ---- epilogue: fp16 (half2) store ----
    int grow = m0 + mbase + (lane >> 2);
    int gcol0 = n0 + nbase + (lane & 3) * 2;
    #pragma unroll
    for (int ni = 0; ni < 8; ++ni) {
        int col = gcol0 + ni * 8;
        #pragma unroll
        for (int mi = 0; mi < 2; ++mi) {
            int r = grow + mi * 16;
            *(__half2*)(C + (size_t)r * C_OUT + col) =
                __floats2half2_rn(acc[mi][ni][0], acc[mi][ni][1]);
            *(__half2*)(C + (size_t)(r + 8) * C_OUT + col) =
                __floats2half2_rn(acc[mi][ni][2], acc[mi][ni][3]);
        }
    }
}

// ---------------- BN stats from fp16 H (row-unrolled x4, 4 independent accumulators) ----------------
// thread t covers channels 2t, 2t+1; rows processed 4 at a time for MLP.
// Deterministic: fixed grouping (r%4 lanes), fixed final combine order.
__global__ __launch_bounds__(256) void stats_kernel(const __half* __restrict__ H)
{
    int r0 = blockIdx.x * 256;
    int t = threadIdx.x;
    const __half2* H2 = (const __half2*)H + (size_t)r0 * (C_OUT/2) + t;
    float sx[4] = {0,0,0,0}, sy[4] = {0,0,0,0};
    float qx[4] = {0,0,0,0}, qy[4] = {0,0,0,0};
    #pragma unroll 4
    for (int r = 0; r < 256; r += 4) {
        float2 v0 = __half22float2(H2[(size_t)(r+0) * (C_OUT/2)]);
        float2 v1 = __half22float2(H2[(size_t)(r+1) * (C_OUT/2)]);
        float2 v2 = __half22float2(H2[(size_t)(r+2) * (C_OUT/2)]);
        float2 v3 = __half22float2(H2[(size_t)(r+3) * (C_OUT/2)]);
        sx[0] += v0.x; qx[0] += v0.x*v0.x; sy[0] += v0.y; qy[0] += v0.y*v0.y;
        sx[1] += v1.x; qx[1] += v1.x*v1.x; sy[1] += v1.y; qy[1] += v1.y*v1.y;
        sx[2] += v2.x; qx[2] += v2.x*v2.x; sy[2] += v2.y; qy[2] += v2.y*v2.y;
        sx[3] += v3.x; qx[3] += v3.x*v3.x; sy[3] += v3.y; qy[3] += v3.y*v3.y;
    }
    float s0 = (sx[0] + sx[1]) + (sx[2] + sx[3]);
    float q0 = (qx[0] + qx[1]) + (qx[2] + qx[3]);
    float s1 = (sy[0] + sy[1]) + (sy[2] + sy[3]);
    float q1 = (qy[0] + qy[1]) + (qy[2] + qy[3]);
    g_psum[blockIdx.x * C_OUT + 2*t]     = s0;
    g_psq [blockIdx.x * C_OUT + 2*t]     = q0;
    g_psum[blockIdx.x * C_OUT + 2*t + 1] = s1;
    g_psq [blockIdx.x * C_OUT + 2*t + 1] = q1;
}

__global__ __launch_bounds__(128) void finalize_kernel(
    const float* __restrict__ g, const float* __restrict__ be,
    float* __restrict__ a, float* __restrict__ c)
{
    int ch = blockIdx.x * 128 + threadIdx.x;
    float s = 0, q = 0;
    for (int p = 0; p < PSTATS; ++p) {
        s += g_psum[p * C_OUT + ch];
        q += g_psq [p * C_OUT + ch];
    }
    float mu  = s * (1.0f / NF_TOT);
    float var = q * (1.0f / NF_TOT) - mu * mu;
    float av  = g[ch] * rsqrtf(var + BN_EPS);
    a[ch] = av;
    c[ch] = be[ch] - mu * av;
}

// ---------------- final BN2 + ReLU + tuple extras (fused, disjoint block ranges) ----------------
__global__ __launch_bounds__(256) void apply_out_kernel(
    const __half* __restrict__ H, const float* __restrict__ pos_skip,
    float* __restrict__ out, int mode)
{
    if (blockIdx.x < HBLOCKS) {
        size_t i = (size_t)blockIdx.x * 256 + threadIdx.x;   // one uint2 = 4 halves
        int cb = (int)(i & (C_OUT/4 - 1));
        uint2 w = ((const uint2*)H)[i];
        float4 av = ((const float4*)g_a2)[cb];
        float4 cv = ((const float4*)g_c2)[cb];
        float2 v0 = __half22float2(*(__half2*)&w.x);
        float2 v1 = __half22float2(*(__half2*)&w.y);
        float4 r;
        r.x = fmaxf(fmaf(av.x, v0.x, cv.x), 0.0f);
        r.y = fmaxf(fmaf(av.y, v0.y, cv.y), 0.0f);
        r.z = fmaxf(fmaf(av.z, v1.x, cv.z), 0.0f);
        r.w = fmaxf(fmaf(av.w, v1.y, cv.w), 0.0f);
        ((float4*)out)[i] = r;
    } else {
        int i = (blockIdx.x - HBLOCKS) * 256 + threadIdx.x;
        const size_t baseH = (size_t)NF_TOT * C_OUT;
        if (i < NF_TOT * 3) out[baseH + i] = pos_skip[i];
        if (i < NF_TOT) {
            if (mode == 1)
                out[baseH + NF_TOT*3 + i] = (float)(i >> 12);
            else if (mode == 2)
                ((long long*)(out + baseH + NF_TOT*3))[i] = (long long)(i >> 12);
        }
    }
}

// ---------------- host ----------------
extern "C" void kernel_launch(void* const* d_in, const int* in_sizes, int n_in,
                              void* d_out, int out_size)
{
    const float* x        = (const float*)d_in[0];
    const float* pos      = (const float*)d_in[1];
    const float* x_skip   = (const float*)d_in[3];
    const float* pos_skip = (const float*)d_in[4];
    const float* W1  = (const float*)d_in[6];
    const float* g1  = (const float*)d_in[8];
    const float* be1 = (const float*)d_in[9];
    const float* W2  = (const float*)d_in[10];
    const float* g2  = (const float*)d_in[12];
    const float* be2 = (const float*)d_in[13];
    float* out = (float*)d_out;

    float *p_a1, *p_c1, *p_a2, *p_c2;
    cudaGetSymbolAddress((void**)&p_a1, g_a1);
    cudaGetSymbolAddress((void**)&p_c1, g_c1);
    cudaGetSymbolAddress((void**)&p_a2, g_a2);
    cudaGetSymbolAddress((void**)&p_c2, g_c2);
    int *p_kidx; float *p_kw;
    cudaGetSymbolAddress((void**)&p_kidx, g_kidx);
    cudaGetSymbolAddress((void**)&p_kw,   g_kw);
    __half *p_h0, *p_h1r, *p_h1h, *p_h2r, *p_w1t, *p_w2t;
    cudaGetSymbolAddress((void**)&p_h0, g_h0);
    cudaGetSymbolAddress((void**)&p_h1r, g_h1r);
    cudaGetSymbolAddress((void**)&p_h1h, g_h1h);
    cudaGetSymbolAddress((void**)&p_h2r, g_h2r);
    cudaGetSymbolAddress((void**)&p_w1t, g_w1t);
    cudaGetSymbolAddress((void**)&p_w2t, g_w2t);

    cudaFuncSetAttribute(gemm_kernel, cudaFuncAttributeMaxDynamicSharedMemorySize, GEMM_SMEM);

    // weight prep (transpose + fp16)
    wsplit_kernel<<<(C_OUT * D_IN + 255) / 256, 256>>>(W1, p_w1t, D_IN, C_OUT);
    wsplit_kernel<<<(C_OUT * C_OUT + 255) / 256, 256>>>(W2, p_w2t, C_OUT, C_OUT);
    // 1) kNN
    knn_kernel<<<NF_TOT / 256, 256>>>(pos, pos_skip, p_kidx, p_kw);
    // 2) interpolate + concat -> h0 (fp16)
    interp_kernel<<<NF_TOT, 128>>>(x, x_skip);
    // 3) GEMM1 -> h1 raw fp16
    {
        dim3 grid(C_OUT / 256, NF_TOT / 128);
        gemm_kernel<<<grid, 512, GEMM_SMEM>>>(p_h0, p_w1t, p_h1r, D_IN, D_IN / BK);
    }
    // 4) BN1 stats (fp16) + affine coefs
    stats_kernel<<<NF_TOT / 256, 256>>>(p_h1r);
    finalize_kernel<<<C_OUT / 128, 128>>>(g1, be1, p_a1, p_c1);
    // 5) BN1+ReLU -> h1 fp16
    h1split_kernel<<<(NF_TOT * (C_OUT / 4)) / 256, 256>>>();
    // 6) GEMM2 -> h2 raw fp16
    {
        dim3 grid(C_OUT / 256, NF_TOT / 128);
        gemm_kernel<<<grid, 512, GEMM_SMEM>>>(p_h1h, p_w2t, p_h2r, C_OUT, C_OUT / BK);
    }
    // 7) BN2 stats (fp16) + affine coefs
    stats_kernel<<<NF_TOT / 256, 256>>>(p_h2r);
    finalize_kernel<<<C_OUT / 128, 128>>>(g2, be2, p_a2, p_c2);
    // 8) BN2 + ReLU -> out, fused with tuple extras
    {
        long long baseH = (long long)NF_TOT * C_OUT;
        long long rem = (long long)out_size - baseH - (long long)NF_TOT * 3;
        int mode = 0;
        if (rem >= 2LL * NF_TOT)      mode = 2;
        else if (rem >= (long long)NF_TOT) mode = 1;
        int xblocks = 0;
        if ((long long)out_size >= baseH + (long long)NF_TOT * 3)
            xblocks = (NF_TOT * 3 + 255) / 256;
        apply_out_kernel<<<HBLOCKS + xblocks, 256>>>(p_h2r, pos_skip, out, mode);
    }
}

// round 17
// speedup vs baseline: 1.0214x; 1.0173x over previous
#include <cuda_runtime.h>
#include <cuda_fp16.h>
#include <cstdint>

// ---------------- problem constants ----------------
#define BATCHES   16
#define NC_PER    1024
#define NF_PER    4096
#define NC_TOT    (BATCHES * NC_PER)   // 16384
#define NF_TOT    (BATCHES * NF_PER)   // 65536
#define C_IN      512
#define C_SKIP    256
#define D_IN      (C_IN + C_SKIP)      // 768
#define C_OUT     512
#define BN_EPS    1e-5f
#define PSTATS    256
#define HBLOCKS   ((NF_TOT * (C_OUT / 4)) / 256)   // 32768 blocks for the h-region
#define W1BLOCKS  ((C_OUT * D_IN) / 256)           // 1536

// ---------------- device scratch ----------------
__device__ __align__(128) __half g_h0[(size_t)NF_TOT * D_IN];
__device__ __align__(128) __half g_h1r[(size_t)NF_TOT * C_OUT];  // raw GEMM1 out (fp16)
__device__ __align__(128) __half g_h1h[(size_t)NF_TOT * C_OUT];  // post-BN1 fp16 (GEMM2 A)
__device__ __align__(128) __half g_h2r[(size_t)NF_TOT * C_OUT];  // raw GEMM2 out (fp16)
__device__ __align__(128) __half g_w1t[(size_t)C_OUT * D_IN];
__device__ __align__(128) __half g_w2t[(size_t)C_OUT * C_OUT];
__device__ int   g_kidx[(size_t)NF_TOT * 3];
__device__ float g_kw[(size_t)NF_TOT * 3];
__device__ float g_psum[PSTATS * C_OUT];
__device__ float g_psq[PSTATS * C_OUT];
__device__ float g_a1[C_OUT], g_c1[C_OUT], g_a2[C_OUT], g_c2[C_OUT];

// ---------------- helpers ----------------
__device__ __forceinline__ uint32_t smem_u32(const void* p) {
    uint32_t a;
    asm("{ .reg .u64 t; cvta.to.shared.u64 t, %1; cvt.u32.u64 %0, t; }" : "=r"(a) : "l"(p));
    return a;
}
__device__ __forceinline__ void cp16(uint32_t dst, const void* src) {
    asm volatile("cp.async.cg.shared.global [%0], [%1], 16;" :: "r"(dst), "l"(src));
}
__device__ __forceinline__ void cp_commit() {
    asm volatile("cp.async.commit_group;" ::: "memory");
}
__device__ __forceinline__ void cp_wait1() {
    asm volatile("cp.async.wait_group 1;" ::: "memory");
}
__device__ __forceinline__ void ldsm4(uint32_t& r0, uint32_t& r1, uint32_t& r2, uint32_t& r3, uint32_t addr) {
    asm volatile("ldmatrix.sync.aligned.m8n8.x4.shared.b16 {%0,%1,%2,%3}, [%4];"
                 : "=r"(r0), "=r"(r1), "=r"(r2), "=r"(r3) : "r"(addr));
}
__device__ __forceinline__ void mma16816(float* c, const uint32_t* a, const uint32_t* b) {
    asm volatile("mma.sync.aligned.m16n8k16.row.col.f32.f16.f16.f32 "
                 "{%0,%1,%2,%3}, {%4,%5,%6,%7}, {%8,%9}, {%0,%1,%2,%3};"
                 : "+f"(c[0]), "+f"(c[1]), "+f"(c[2]), "+f"(c[3])
                 : "r"(a[0]), "r"(a[1]), "r"(a[2]), "r"(a[3]), "r"(b[0]), "r"(b[1]));
}

// ---------------- kNN (K=3) ----------------
__global__ __launch_bounds__(256) void knn_kernel(
    const float* __restrict__ pos, const float* __restrict__ pos_skip,
    int* __restrict__ idx_out, float* __restrict__ w_out)
{
    __shared__ float sx[NC_PER], sy[NC_PER], sz[NC_PER], sn[NC_PER];
    int blk = blockIdx.x;
    int b = blk >> 4;
    const float* pc = pos + (size_t)b * NC_PER * 3;
    for (int i = threadIdx.x; i < NC_PER; i += 256) {
        float px = pc[i*3+0], py = pc[i*3+1], pz = pc[i*3+2];
        sx[i] = px; sy[i] = py; sz[i] = pz;
        sn[i] = px*px + py*py + pz*pz;
    }
    __syncthreads();
    int f = blk * 256 + threadIdx.x;
    float fx = pos_skip[f*3+0], fy = pos_skip[f*3+1], fz = pos_skip[f*3+2];
    float fn = fx*fx + fy*fy + fz*fz;
    float d0 = 3.4e38f, d1 = 3.4e38f, d2 = 3.4e38f;
    int   i0 = 0, i1 = 0, i2 = 0;
    for (int c = 0; c < NC_PER; ++c) {
        float dot = fx*sx[c] + fy*sy[c] + fz*sz[c];
        float dd  = fn + sn[c] - 2.0f*dot;
        if (dd < d2) {
            if (dd < d1) {
                if (dd < d0) { d2=d1; i2=i1; d1=d0; i1=i0; d0=dd; i0=c; }
                else         { d2=d1; i2=i1; d1=dd; i1=c; }
            } else           { d2=dd; i2=c; }
        }
    }
    float w0 = 1.0f / fmaxf(d0, 1e-16f);
    float w1 = 1.0f / fmaxf(d1, 1e-16f);
    float w2 = 1.0f / fmaxf(d2, 1e-16f);
    float inv = 1.0f / (w0 + w1 + w2);
    idx_out[f*3+0] = b * NC_PER + i0;
    idx_out[f*3+1] = b * NC_PER + i1;
    idx_out[f*3+2] = b * NC_PER + i2;
    w_out[f*3+0] = w0 * inv;
    w_out[f*3+1] = w1 * inv;
    w_out[f*3+2] = w2 * inv;
}

// ---------------- interpolate + concat -> fp16 h0 ----------------
__global__ __launch_bounds__(128) void interp_kernel(
    const float* __restrict__ x, const float* __restrict__ x_skip)
{
    int f = blockIdx.x;
    int t = threadIdx.x;
    int ia = g_kidx[f*3+0], ib = g_kidx[f*3+1], ic = g_kidx[f*3+2];
    float w0 = g_kw[f*3+0], w1 = g_kw[f*3+1], w2 = g_kw[f*3+2];
    float4 a = ((const float4*)(x + (size_t)ia * C_IN))[t];
    float4 b = ((const float4*)(x + (size_t)ib * C_IN))[t];
    float4 c = ((const float4*)(x + (size_t)ic * C_IN))[t];
    __half h[4];
    h[0] = __float2half_rn(w0*a.x + w1*b.x + w2*c.x);
    h[1] = __float2half_rn(w0*a.y + w1*b.y + w2*c.y);
    h[2] = __float2half_rn(w0*a.z + w1*b.z + w2*c.z);
    h[3] = __float2half_rn(w0*a.w + w1*b.w + w2*c.w);
    *(uint2*)(g_h0 + (size_t)f * D_IN + t * 4) = *(uint2*)h;
    if (t < C_SKIP / 4) {
        float4 s = ((const float4*)(x_skip + (size_t)f * C_SKIP))[t];
        h[0] = __float2half_rn(s.x);
        h[1] = __float2half_rn(s.y);
        h[2] = __float2half_rn(s.z);
        h[3] = __float2half_rn(s.w);
        *(uint2*)(g_h0 + (size_t)f * D_IN + C_IN + t * 4) = *(uint2*)h;
    }
}

// ---------------- W1+W2 transpose -> fp16 in one launch ----------------
// blocks [0, W1BLOCKS): W1t[n][k] = W1[k][n]; rest: W2t.
__global__ __launch_bounds__(256) void wsplit_kernel(
    const float* __restrict__ W1, const float* __restrict__ W2)
{
    if (blockIdx.x < W1BLOCKS) {
        int id = blockIdx.x * 256 + threadIdx.x;       // over C_OUT*D_IN
        int n = id / D_IN, k = id % D_IN;
        g_w1t[id] = __float2half_rn(W1[(size_t)k * C_OUT + n]);
    } else {
        int id = (blockIdx.x - W1BLOCKS) * 256 + threadIdx.x;  // over C_OUT*C_OUT
        int n = id / C_OUT, k = id % C_OUT;
        g_w2t[id] = __float2half_rn(W2[(size_t)k * C_OUT + n]);
    }
}

// ---------------- h1r (fp16) -> BN1+ReLU -> fp16 ----------------
__global__ __launch_bounds__(256) void h1split_kernel()
{
    size_t i = (size_t)blockIdx.x * 256 + threadIdx.x;   // one uint2 = 4 halves
    int cb = (int)(i & (C_OUT/4 - 1));
    uint2 w = ((const uint2*)g_h1r)[i];
    float4 av = ((const float4*)g_a1)[cb];
    float4 cv = ((const float4*)g_c1)[cb];
    float2 v0 = __half22float2(*(__half2*)&w.x);
    float2 v1 = __half22float2(*(__half2*)&w.y);
    __half h[4];
    h[0] = __float2half_rn(fmaxf(fmaf(av.x, v0.x, cv.x), 0.0f));
    h[1] = __float2half_rn(fmaxf(fmaf(av.y, v0.y, cv.y), 0.0f));
    h[2] = __float2half_rn(fmaxf(fmaf(av.z, v1.x, cv.z), 0.0f));
    h[3] = __float2half_rn(fmaxf(fmaf(av.w, v1.y, cv.w), 0.0f));
    ((uint2*)g_h1h)[i] = *(uint2*)h;
}

// ---------------- fp16 HGEMM: 128(M)x256(N) tile, 512 thr, 3-stage, fp16 out ----------------
// C[M,512] = A[M,Kd] @ Wt[512,Kd]^T       (bias dropped: BN shift-invariant)
#define BK 64
#define A_BYTES 16384                    // 128x64 fp16
#define B_BYTES 32768                    // 256x64 fp16
#define STAGE_BYTES (A_BYTES + B_BYTES)  // 49152
#define STAGES 3
#define GEMM_SMEM (STAGES * STAGE_BYTES) // 147456

__device__ __forceinline__ uint32_t swoff(int row, int c) {
    return (uint32_t)(row * 128 + ((c ^ (row & 7)) << 4));
}

__global__ __launch_bounds__(512, 1) void gemm_kernel(
    const __half* __restrict__ A, const __half* __restrict__ B,
    __half* __restrict__ C, int Kd, int nchunk)
{
    extern __shared__ __align__(128) char smem[];
    uint32_t sbase = smem_u32(smem);
    int tid  = threadIdx.x;
    int wid  = tid >> 5, lane = tid & 31;
    int m0 = blockIdx.y * 128;
    int n0 = blockIdx.x * 256;

    const __half* asrc = A + (size_t)m0 * Kd;
    const __half* bsrc = B + (size_t)n0 * Kd;

    auto issue = [&](int sidx, int k0) {
        uint32_t sb = sbase + (uint32_t)sidx * STAGE_BYTES;
        #pragma unroll
        for (int it = 0; it < 2; ++it) {             // A: 128 rows x 8 chunks
            int chunk = it * 512 + tid;
            int row = chunk >> 3, c = chunk & 7;
            cp16(sb + swoff(row, c), asrc + (size_t)row * Kd + k0 + c * 8);
        }
        uint32_t rb = sb + A_BYTES;                  // B: 256 rows x 8 chunks
        #pragma unroll
        for (int it = 0; it < 4; ++it) {
            int chunk = it * 512 + tid;
            int row = chunk >> 3, c = chunk & 7;
            cp16(rb + swoff(row, c), bsrc + (size_t)row * Kd + k0 + c * 8);
        }
    };

    issue(0, 0);   cp_commit();
    issue(1, BK);  cp_commit();

    // warp tiling: 4 (M) x 4 (N) warps; warp tile 32(M) x 64(N)
    int wm = wid & 3, wn = wid >> 2;
    int mbase = wm * 32, nbase = wn * 64;
    int sub = lane >> 3, l7 = lane & 7;

    float acc[2][8][4];
    #pragma unroll
    for (int i = 0; i < 2; ++i)
        #pragma unroll
        for (int j = 0; j < 8; ++j)
            #pragma unroll
            for (int q = 0; q < 4; ++q) acc[i][j][q] = 0.0f;

    int arow_l = mbase + ((sub & 1) << 3) + l7;
    int acol_s = (sub >> 1);
    int brow_l = nbase + ((sub >> 1) << 3) + l7;
    int bcol_s = (sub & 1);

    for (int cc = 0; cc < nchunk; ++cc) {
        cp_wait1();
        __syncthreads();
        if (cc + 2 < nchunk) issue((cc + 2) % STAGES, (cc + 2) * BK);
        cp_commit();

        uint32_t bb = sbase + (uint32_t)(cc % STAGES) * STAGE_BYTES;
        #pragma unroll
        for (int ks = 0; ks < 4; ++ks) {
            int achunk = ks * 2 + acol_s;
            int bchunk = ks * 2 + bcol_s;
            uint32_t ah[2][4], bh[8][2];
            #pragma unroll
            for (int mi = 0; mi < 2; ++mi) {
                uint32_t ao = swoff(arow_l + mi * 16, achunk);
                ldsm4(ah[mi][0], ah[mi][1], ah[mi][2], ah[mi][3], bb + ao);
            }
            #pragma unroll
            for (int pi = 0; pi < 4; ++pi) {
                uint32_t bo = swoff(brow_l + pi * 16, bchunk);
                ldsm4(bh[pi*2][0], bh[pi*2][1], bh[pi*2+1][0], bh[pi*2+1][1],
                      bb + A_BYTES + bo);
            }
            #pragma unroll
            for (int mi = 0; mi < 2; ++mi)
                #pragma unroll
                for (int ni = 0; ni < 8; ++ni)
                    mma16816(acc[mi][ni], ah[mi], bh[ni]);
        }
    }

    // ---- epilogue: fp16 (half2) store ----
    int grow = m0 + mbase + (lane >> 2);
    int gcol0 = n0 + nbase + (lane & 3) * 2;
    #pragma unroll
    for (int ni = 0; ni < 8; ++ni) {
        int col = gcol0 + ni * 8;
        #pragma unroll
        for (int mi = 0; mi < 2; ++mi) {
            int r = grow + mi * 16;
            *(__half2*)(C + (size_t)r * C_OUT + col) =
                __floats2half2_rn(acc[mi][ni][0], acc[mi][ni][1]);
            *(__half2*)(C + (size_t)(r + 8) * C_OUT + col) =
                __floats2half2_rn(acc[mi][ni][2], acc[mi][ni][3]);
        }
    }
}

// ---------------- BN stats from fp16 H (two-stage, deterministic) ----------------
// thread t covers channels 2t, 2t+1 (one half2 per row)
__global__ __launch_bounds__(256) void stats_kernel(const __half* __restrict__ H)
{
    int r0 = blockIdx.x * 256;
    int t = threadIdx.x;
    float s0 = 0, q0 = 0, s1 = 0, q1 = 0;
    const __half2* H2 = (const __half2*)H;
    for (int r = r0; r < r0 + 256; ++r) {
        float2 v = __half22float2(H2[(size_t)r * (C_OUT/2) + t]);
        s0 += v.x; q0 += v.x*v.x;
        s1 += v.y; q1 += v.y*v.y;
    }
    g_psum[blockIdx.x * C_OUT + 2*t]     = s0;
    g_psq [blockIdx.x * C_OUT + 2*t]     = q0;
    g_psum[blockIdx.x * C_OUT + 2*t + 1] = s1;
    g_psq [blockIdx.x * C_OUT + 2*t + 1] = q1;
}

__global__ __launch_bounds__(128) void finalize_kernel(
    const float* __restrict__ g, const float* __restrict__ be,
    float* __restrict__ a, float* __restrict__ c)
{
    int ch = blockIdx.x * 128 + threadIdx.x;
    float s = 0, q = 0;
    for (int p = 0; p < PSTATS; ++p) {
        s += g_psum[p * C_OUT + ch];
        q += g_psq [p * C_OUT + ch];
    }
    float mu  = s * (1.0f / NF_TOT);
    float var = q * (1.0f / NF_TOT) - mu * mu;
    float av  = g[ch] * rsqrtf(var + BN_EPS);
    a[ch] = av;
    c[ch] = be[ch] - mu * av;
}

// ---------------- final BN2 + ReLU + tuple extras (fused, disjoint block ranges) ----------------
__global__ __launch_bounds__(256) void apply_out_kernel(
    const __half* __restrict__ H, const float* __restrict__ pos_skip,
    float* __restrict__ out, int mode)
{
    if (blockIdx.x < HBLOCKS) {
        size_t i = (size_t)blockIdx.x * 256 + threadIdx.x;   // one uint2 = 4 halves
        int cb = (int)(i & (C_OUT/4 - 1));
        uint2 w = ((const uint2*)H)[i];
        float4 av = ((const float4*)g_a2)[cb];
        float4 cv = ((const float4*)g_c2)[cb];
        float2 v0 = __half22float2(*(__half2*)&w.x);
        float2 v1 = __half22float2(*(__half2*)&w.y);
        float4 r;
        r.x = fmaxf(fmaf(av.x, v0.x, cv.x), 0.0f);
        r.y = fmaxf(fmaf(av.y, v0.y, cv.y), 0.0f);
        r.z = fmaxf(fmaf(av.z, v1.x, cv.z), 0.0f);
        r.w = fmaxf(fmaf(av.w, v1.y, cv.w), 0.0f);
        ((float4*)out)[i] = r;
    } else {
        int i = (blockIdx.x - HBLOCKS) * 256 + threadIdx.x;
        const size_t baseH = (size_t)NF_TOT * C_OUT;
        if (i < NF_TOT * 3) out[baseH + i] = pos_skip[i];
        if (i < NF_TOT) {
            if (mode == 1)
                out[baseH + NF_TOT*3 + i] = (float)(i >> 12);
            else if (mode == 2)
                ((long long*)(out + baseH + NF_TOT*3))[i] = (long long)(i >> 12);
        }
    }
}

// ---------------- host ----------------
extern "C" void kernel_launch(void* const* d_in, const int* in_sizes, int n_in,
                              void* d_out, int out_size)
{
    const float* x        = (const float*)d_in[0];
    const float* pos      = (const float*)d_in[1];
    const float* x_skip   = (const float*)d_in[3];
    const float* pos_skip = (const float*)d_in[4];
    const float* W1  = (const float*)d_in[6];
    const float* g1  = (const float*)d_in[8];
    const float* be1 = (const float*)d_in[9];
    const float* W2  = (const float*)d_in[10];
    const float* g2  = (const float*)d_in[12];
    const float* be2 = (const float*)d_in[13];
    float* out = (float*)d_out;

    float *p_a1, *p_c1, *p_a2, *p_c2;
    cudaGetSymbolAddress((void**)&p_a1, g_a1);
    cudaGetSymbolAddress((void**)&p_c1, g_c1);
    cudaGetSymbolAddress((void**)&p_a2, g_a2);
    cudaGetSymbolAddress((void**)&p_c2, g_c2);
    int *p_kidx; float *p_kw;
    cudaGetSymbolAddress((void**)&p_kidx, g_kidx);
    cudaGetSymbolAddress((void**)&p_kw,   g_kw);
    __half *p_h0, *p_h1r, *p_h1h, *p_h2r, *p_w1t, *p_w2t;
    cudaGetSymbolAddress((void**)&p_h0, g_h0);
    cudaGetSymbolAddress((void**)&p_h1r, g_h1r);
    cudaGetSymbolAddress((void**)&p_h1h, g_h1h);
    cudaGetSymbolAddress((void**)&p_h2r, g_h2r);
    cudaGetSymbolAddress((void**)&p_w1t, g_w1t);
    cudaGetSymbolAddress((void**)&p_w2t, g_w2t);

    cudaFuncSetAttribute(gemm_kernel, cudaFuncAttributeMaxDynamicSharedMemorySize, GEMM_SMEM);

    // weight prep (transpose + fp16), both W1 and W2 in one launch
    wsplit_kernel<<<W1BLOCKS + (C_OUT * C_OUT) / 256, 256>>>(W1, W2);
    // 1) kNN
    knn_kernel<<<NF_TOT / 256, 256>>>(pos, pos_skip, p_kidx, p_kw);
    // 2) interpolate + concat -> h0 (fp16)
    interp_kernel<<<NF_TOT, 128>>>(x, x_skip);
    // 3) GEMM1 -> h1 raw fp16
    {
        dim3 grid(C_OUT / 256, NF_TOT / 128);
        gemm_kernel<<<grid, 512, GEMM_SMEM>>>(p_h0, p_w1t, p_h1r, D_IN, D_IN / BK);
    }
    // 4) BN1 stats (fp16) + affine coefs
    stats_kernel<<<NF_TOT / 256, 256>>>(p_h1r);
    finalize_kernel<<<C_OUT / 128, 128>>>(g1, be1, p_a1, p_c1);
    // 5) BN1+ReLU -> h1 fp16
    h1split_kernel<<<(NF_TOT * (C_OUT / 4)) / 256, 256>>>();
    // 6) GEMM2 -> h2 raw fp16
    {
        dim3 grid(C_OUT / 256, NF_TOT / 128);
        gemm_kernel<<<grid, 512, GEMM_SMEM>>>(p_h1h, p_w2t, p_h2r, C_OUT, C_OUT / BK);
    }
    // 7) BN2 stats (fp16) + affine coefs
    stats_kernel<<<NF_TOT / 256, 256>>>(p_h2r);
    finalize_kernel<<<C_OUT / 128, 128>>>(g2, be2, p_a2, p_c2);
    // 8) BN2 + ReLU -> out, fused with tuple extras
    {
        long long baseH = (long long)NF_TOT * C_OUT;
        long long rem = (long long)out_size - baseH - (long long)NF_TOT * 3;
        int mode = 0;
        if (rem >= 2LL * NF_TOT)      mode = 2;
        else if (rem >= (long long)NF_TOT) mode = 1;
        int xblocks = 0;
        if ((long long)out_size >= baseH + (long long)NF_TOT * 3)
            xblocks = (NF_TOT * 3 + 255) / 256;
        apply_out_kernel<<<HBLOCKS + xblocks, 256>>>(p_h2r, pos_skip, out, mode);
    }
}